// round 6
// baseline (speedup 1.0000x reference)
#include <cuda_runtime.h>
#include <cuda_bf16.h>
#include <cstdint>

#define N_NODES 40000
#define DIMF    128
#define N_EDGES 640000

// ---- scratch (no allocs allowed) ----
__device__ int   g_deg[N_NODES];          // in-degree (int)
__device__ int   g_off[N_NODES];          // CSR offsets
__device__ int   g_cur[N_NODES];          // scatter cursors
__device__ float g_cnt[N_NODES];          // in-degree (float, for GEMM)
__device__ int   g_esrc[N_EDGES];         // src indices sorted by dst
__device__ float g_agg[N_NODES * DIMF];   // neighbor-sum buffer
__device__ float g_h[N_NODES * DIMF];     // layer-1 output

// ---------------------------------------------------------------------------
// CSR build (once per call; graph shared by both layers)
// ---------------------------------------------------------------------------
__global__ void init_deg_kernel() {
    int i = blockIdx.x * blockDim.x + threadIdx.x;
    if (i < N_NODES) g_deg[i] = 0;
}

__global__ void hist_kernel(const int* __restrict__ ei) {
    int e = blockIdx.x * blockDim.x + threadIdx.x;
    if (e >= N_EDGES) return;
    int d = ei[N_EDGES + e];
    if ((unsigned)d < N_NODES) atomicAdd(&g_deg[d], 1);
}

// single-block exclusive prefix scan over 40k degrees; also emits cur + float cnt
__global__ __launch_bounds__(1024) void prefix_kernel() {
    __shared__ int ssum[1024];
    const int t  = threadIdx.x;
    const int CH = (N_NODES + 1023) / 1024;      // 40
    const int base = t * CH;

    int s = 0;
    for (int i = 0; i < CH; ++i) {
        int idx = base + i;
        if (idx < N_NODES) s += g_deg[idx];
    }
    ssum[t] = s;
    __syncthreads();
    // Hillis-Steele inclusive scan
    for (int d = 1; d < 1024; d <<= 1) {
        int v = (t >= d) ? ssum[t - d] : 0;
        __syncthreads();
        ssum[t] += v;
        __syncthreads();
    }
    int run = (t == 0) ? 0 : ssum[t - 1];
    for (int i = 0; i < CH; ++i) {
        int idx = base + i;
        if (idx >= N_NODES) break;
        int dg = g_deg[idx];
        g_off[idx] = run;
        g_cur[idx] = run;
        g_cnt[idx] = (float)dg;
        run += dg;
    }
}

__global__ void sort_kernel(const int* __restrict__ ei) {
    int e = blockIdx.x * blockDim.x + threadIdx.x;
    if (e >= N_EDGES) return;
    int s = ei[e];
    int d = ei[N_EDGES + e];
    if ((unsigned)s >= N_NODES || (unsigned)d >= N_NODES) return;
    int pos = atomicAdd(&g_cur[d], 1);
    g_esrc[pos] = s;
}

// ---------------------------------------------------------------------------
// aggregate: one warp per dst node. Gather src rows (float4/lane), register-
// accumulate, single 512B store. No atomics, no zero-init needed.
// ---------------------------------------------------------------------------
__global__ __launch_bounds__(256) void agg_kernel(const float* __restrict__ feat) {
    const int w    = blockIdx.x * (blockDim.x >> 5) + (threadIdx.x >> 5);
    const int lane = threadIdx.x & 31;
    if (w >= N_NODES) return;

    const int deg   = g_deg[w];
    const int start = g_off[w];

    float4 acc = make_float4(0.f, 0.f, 0.f, 0.f);
    int i = 0;
    for (; i + 4 <= deg; i += 4) {
        int s0 = __ldg(&g_esrc[start + i + 0]);
        int s1 = __ldg(&g_esrc[start + i + 1]);
        int s2 = __ldg(&g_esrc[start + i + 2]);
        int s3 = __ldg(&g_esrc[start + i + 3]);
        float4 v0 = reinterpret_cast<const float4*>(feat + (size_t)s0 * DIMF)[lane];
        float4 v1 = reinterpret_cast<const float4*>(feat + (size_t)s1 * DIMF)[lane];
        float4 v2 = reinterpret_cast<const float4*>(feat + (size_t)s2 * DIMF)[lane];
        float4 v3 = reinterpret_cast<const float4*>(feat + (size_t)s3 * DIMF)[lane];
        acc.x += v0.x + v1.x + v2.x + v3.x;
        acc.y += v0.y + v1.y + v2.y + v3.y;
        acc.z += v0.z + v1.z + v2.z + v3.z;
        acc.w += v0.w + v1.w + v2.w + v3.w;
    }
    for (; i < deg; ++i) {
        int s = __ldg(&g_esrc[start + i]);
        float4 v = reinterpret_cast<const float4*>(feat + (size_t)s * DIMF)[lane];
        acc.x += v.x; acc.y += v.y; acc.z += v.z; acc.w += v.w;
    }
    reinterpret_cast<float4*>(g_agg + (size_t)w * DIMF)[lane] = acc;
}

// ---------------------------------------------------------------------------
// Tensor-core (tf32 mma.sync) fused SAGE GEMM with on-the-fly mean norm:
//   out[m][n] = relu( (1/max(cnt[m],1)) * sum_k A0[m][k]*W0[n][k]
//                    + sum_k A1[m][k]*W1[n][k] + bias[n] )
// BM=128, BN=128(all of N), BK=16, logical K=256 (two mats).
// ---------------------------------------------------------------------------
#define BM 128
#define BK 16
#define LDP 132   // padded smem row stride (uint32 elems)

__device__ __forceinline__ uint32_t f2tf32(float v) {
    uint32_t t;
    asm("cvt.rna.tf32.f32 %0, %1;" : "=r"(t) : "f"(v));
    return t;
}

__global__ __launch_bounds__(256, 2) void gemm_tc_kernel(
        const float* A0, const float* __restrict__ A1,
        const float* __restrict__ cnt,
        const float* __restrict__ W0, const float* __restrict__ W1,
        const float* __restrict__ bias, float* __restrict__ out) {
    __shared__ uint32_t As[BK * LDP];
    __shared__ uint32_t Bs[BK * LDP];

    const int tid   = threadIdx.x;
    const int m0    = blockIdx.x * BM;
    const int lane  = tid & 31;
    const int warp  = tid >> 5;
    const int warpM = warp & 1;
    const int warpN = warp >> 1;
    const int lr    = lane >> 2;
    const int lc    = lane & 3;

    const int r0 = tid >> 2;
    const int r1 = r0 + 64;
    const int q  = tid & 3;

    const int gm0 = m0 + r0, gm1 = m0 + r1;
    const float s0 = (gm0 < N_NODES) ? __frcp_rn(fmaxf(__ldg(&cnt[gm0]), 1.f)) : 0.f;
    const float s1 = (gm1 < N_NODES) ? __frcp_rn(fmaxf(__ldg(&cnt[gm1]), 1.f)) : 0.f;

    float acc[4][4][4];
#pragma unroll
    for (int i = 0; i < 4; ++i)
#pragma unroll
        for (int j = 0; j < 4; ++j)
#pragma unroll
            for (int f = 0; f < 4; ++f) acc[i][j][f] = 0.f;

    const float4 f4z = make_float4(0.f, 0.f, 0.f, 0.f);
    float4 a0r, a1r, b0r, b1r;

    auto load_tile = [&](int kt, float4& av0, float4& av1, float4& bv0, float4& bv1) {
        const float* A = (kt < 8) ? A0 : A1;
        const float* W = (kt < 8) ? W0 : W1;
        const float sc0 = (kt < 8) ? s0 : 1.f;
        const float sc1 = (kt < 8) ? s1 : 1.f;
        const int k0 = (kt & 7) * BK + q * 4;
        av0 = (gm0 < N_NODES) ? *reinterpret_cast<const float4*>(A + (size_t)gm0 * DIMF + k0) : f4z;
        av1 = (gm1 < N_NODES) ? *reinterpret_cast<const float4*>(A + (size_t)gm1 * DIMF + k0) : f4z;
        av0.x *= sc0; av0.y *= sc0; av0.z *= sc0; av0.w *= sc0;
        av1.x *= sc1; av1.y *= sc1; av1.z *= sc1; av1.w *= sc1;
        bv0 = *reinterpret_cast<const float4*>(W + (size_t)r0 * DIMF + k0);
        bv1 = *reinterpret_cast<const float4*>(W + (size_t)r1 * DIMF + k0);
    };

    load_tile(0, a0r, a1r, b0r, b1r);

#pragma unroll 1
    for (int kt = 0; kt < 16; ++kt) {
        __syncthreads();
        const int kb = q * 4;
        As[(kb + 0) * LDP + r0] = f2tf32(a0r.x);  As[(kb + 1) * LDP + r0] = f2tf32(a0r.y);
        As[(kb + 2) * LDP + r0] = f2tf32(a0r.z);  As[(kb + 3) * LDP + r0] = f2tf32(a0r.w);
        As[(kb + 0) * LDP + r1] = f2tf32(a1r.x);  As[(kb + 1) * LDP + r1] = f2tf32(a1r.y);
        As[(kb + 2) * LDP + r1] = f2tf32(a1r.z);  As[(kb + 3) * LDP + r1] = f2tf32(a1r.w);
        Bs[(kb + 0) * LDP + r0] = f2tf32(b0r.x);  Bs[(kb + 1) * LDP + r0] = f2tf32(b0r.y);
        Bs[(kb + 2) * LDP + r0] = f2tf32(b0r.z);  Bs[(kb + 3) * LDP + r0] = f2tf32(b0r.w);
        Bs[(kb + 0) * LDP + r1] = f2tf32(b1r.x);  Bs[(kb + 1) * LDP + r1] = f2tf32(b1r.y);
        Bs[(kb + 2) * LDP + r1] = f2tf32(b1r.z);  Bs[(kb + 3) * LDP + r1] = f2tf32(b1r.w);
        __syncthreads();

        if (kt < 15) load_tile(kt + 1, a0r, a1r, b0r, b1r);

#pragma unroll
        for (int s = 0; s < BK; s += 8) {
            uint32_t bf0[4], bf1[4];
#pragma unroll
            for (int nt = 0; nt < 4; ++nt) {
                const int n = warpN * 32 + nt * 8 + lr;
                bf0[nt] = Bs[(s + lc) * LDP + n];
                bf1[nt] = Bs[(s + lc + 4) * LDP + n];
            }
#pragma unroll
            for (int mt = 0; mt < 4; ++mt) {
                const int m = warpM * 64 + mt * 16 + lr;
                uint32_t a0 = As[(s + lc) * LDP + m];
                uint32_t a1 = As[(s + lc) * LDP + m + 8];
                uint32_t a2 = As[(s + lc + 4) * LDP + m];
                uint32_t a3 = As[(s + lc + 4) * LDP + m + 8];
#pragma unroll
                for (int nt = 0; nt < 4; ++nt) {
                    asm volatile(
                        "mma.sync.aligned.m16n8k8.row.col.f32.tf32.tf32.f32 "
                        "{%0,%1,%2,%3}, {%4,%5,%6,%7}, {%8,%9}, {%0,%1,%2,%3};"
                        : "+f"(acc[mt][nt][0]), "+f"(acc[mt][nt][1]),
                          "+f"(acc[mt][nt][2]), "+f"(acc[mt][nt][3])
                        : "r"(a0), "r"(a1), "r"(a2), "r"(a3),
                          "r"(bf0[nt]), "r"(bf1[nt]));
                }
            }
        }
    }

    // epilogue: + bias, relu
#pragma unroll
    for (int nt = 0; nt < 4; ++nt) {
        const int n = warpN * 32 + nt * 8 + 2 * lc;
        const float bv0 = __ldg(&bias[n]);
        const float bv1 = __ldg(&bias[n + 1]);
#pragma unroll
        for (int mt = 0; mt < 4; ++mt) {
            const int r = m0 + warpM * 64 + mt * 16 + lr;
            if (r < N_NODES) {
                float2 v;
                v.x = fmaxf(acc[mt][nt][0] + bv0, 0.f);
                v.y = fmaxf(acc[mt][nt][1] + bv1, 0.f);
                *reinterpret_cast<float2*>(out + (size_t)r * DIMF + n) = v;
            }
            if (r + 8 < N_NODES) {
                float2 v;
                v.x = fmaxf(acc[mt][nt][2] + bv0, 0.f);
                v.y = fmaxf(acc[mt][nt][3] + bv1, 0.f);
                *reinterpret_cast<float2*>(out + (size_t)(r + 8) * DIMF + n) = v;
            }
        }
    }
}

// ---------------------------------------------------------------------------
// launch
// ---------------------------------------------------------------------------
extern "C" void kernel_launch(void* const* d_in, const int* in_sizes, int n_in,
                              void* d_out, int out_size) {
    const float* x   = (const float*)d_in[0];
    const int*   ei  = (const int*)d_in[1];
    const float* W1l = (const float*)d_in[2];
    const float* b1l = (const float*)d_in[3];
    const float* W1r = (const float*)d_in[4];
    const float* W2l = (const float*)d_in[5];
    const float* b2l = (const float*)d_in[6];
    const float* W2r = (const float*)d_in[7];
    float* out = (float*)d_out;

    const int node_grid = (N_NODES + 255) / 256;
    const int edge_grid = (N_EDGES + 255) / 256;
    const int agg_grid  = (N_NODES + 7) / 8;             // warp per node, 8 warps/blk
    const int gemm_grid = (N_NODES + BM - 1) / BM;       // 313

    static float* p_agg = nullptr;
    static float* p_h   = nullptr;
    static float* p_cnt = nullptr;
    if (!p_agg) {
        cudaGetSymbolAddress((void**)&p_agg, g_agg);
        cudaGetSymbolAddress((void**)&p_h,   g_h);
        cudaGetSymbolAddress((void**)&p_cnt, g_cnt);
    }

    // ---- CSR build (shared by both layers) ----
    init_deg_kernel<<<node_grid, 256>>>();
    hist_kernel<<<edge_grid, 256>>>(ei);
    prefix_kernel<<<1, 1024>>>();
    sort_kernel<<<edge_grid, 256>>>(ei);

    // ---- layer 1 ----
    agg_kernel<<<agg_grid, 256>>>(x);
    gemm_tc_kernel<<<gemm_grid, 256>>>(p_agg, x, p_cnt, W1l, W1r, b1l, p_h);

    // ---- layer 2 ----
    agg_kernel<<<agg_grid, 256>>>(p_h);
    gemm_tc_kernel<<<gemm_grid, 256>>>(p_agg, p_h, p_cnt, W2l, W2r, b2l, out);
}